// round 2
// baseline (speedup 1.0000x reference)
#include <cuda_runtime.h>
#include <cuda_bf16.h>

#define N_NODES 100000
#define N_EDGES 1600000
#define IN_CH   128
#define NG      16

// ---------------- scratch (device globals; no allocation allowed) -----------
__device__ float g_y  [N_NODES * 64];   // x @ W_l^T
__device__ float g_xr [N_NODES * 64];   // x @ W_r^T
__device__ float g_agg[N_NODES * 64];   // segment_sum of y over dst
__device__ float g_deg[N_NODES];
__device__ float g_gsum[NG * 64];
__device__ float g_gcnt[NG];

// ---------------- kernel 1: zero scratch ------------------------------------
__global__ void zero_kernel() {
    int i = blockIdx.x * blockDim.x + threadIdx.x;
    int stride = gridDim.x * blockDim.x;
    float4 z4 = make_float4(0.f, 0.f, 0.f, 0.f);
    float4* a4 = reinterpret_cast<float4*>(g_agg);
    for (int j = i; j < N_NODES * 16; j += stride) a4[j] = z4;
    for (int j = i; j < N_NODES; j += stride) g_deg[j] = 0.f;
    for (int j = i; j < NG * 64; j += stride) g_gsum[j] = 0.f;
    for (int j = i; j < NG; j += stride) g_gcnt[j] = 0.f;
}

// ---------------- kernel 2: fused node GEMM ---------------------------------
// C[n, 0:128] = x[n,:] @ Wcat^T   where Wcat = [W_l ; W_r]  (each 64x128)
// Output split: j<64 -> g_y, j>=64 -> g_xr.
// Tile: 64 nodes x 128 outs per block, 256 threads, 4x8 micro-tile/thread.
#define GEMM_BM 64
__global__ void node_gemm(const float* __restrict__ x,
                          const float* __restrict__ Wl,
                          const float* __restrict__ Wr) {
    extern __shared__ float smem[];
    float* Ws = smem;              // [128][128]  WsT[k][j] = Wcat[j][k]
    float* Xs = smem + 128 * 128;  // [64][132]

    int tid = threadIdx.x;

    // load W transposed into shared
    for (int idx = tid; idx < 128 * 128; idx += 256) {
        int j = idx >> 7, k = idx & 127;
        float v = (j < 64) ? Wl[j * 128 + k] : Wr[(j - 64) * 128 + k];
        Ws[k * 128 + j] = v;
    }

    int nodeBase = blockIdx.x * GEMM_BM;
    for (int idx = tid; idx < GEMM_BM * 128; idx += 256) {
        int r = idx >> 7, k = idx & 127;
        int n = nodeBase + r;
        Xs[r * 132 + k] = (n < N_NODES) ? x[(size_t)n * 128 + k] : 0.f;
    }
    __syncthreads();

    int ty = tid >> 4;   // 0..15 : rows ty*4 .. ty*4+3
    int tx = tid & 15;   // 0..15 : cols tx*8 .. tx*8+7

    float acc[4][8];
#pragma unroll
    for (int r = 0; r < 4; r++)
#pragma unroll
        for (int c = 0; c < 8; c++) acc[r][c] = 0.f;

#pragma unroll 4
    for (int k = 0; k < 128; k++) {
        float xv[4];
#pragma unroll
        for (int r = 0; r < 4; r++) xv[r] = Xs[(ty * 4 + r) * 132 + k];
        float4 w0 = *reinterpret_cast<const float4*>(&Ws[k * 128 + tx * 8]);
        float4 w1 = *reinterpret_cast<const float4*>(&Ws[k * 128 + tx * 8 + 4]);
        float wv[8] = {w0.x, w0.y, w0.z, w0.w, w1.x, w1.y, w1.z, w1.w};
#pragma unroll
        for (int r = 0; r < 4; r++)
#pragma unroll
            for (int c = 0; c < 8; c++) acc[r][c] = fmaf(xv[r], wv[c], acc[r][c]);
    }

    int j = tx * 8;
#pragma unroll
    for (int r = 0; r < 4; r++) {
        int n = nodeBase + ty * 4 + r;
        if (n >= N_NODES) continue;
        float4 o0 = make_float4(acc[r][0], acc[r][1], acc[r][2], acc[r][3]);
        float4 o1 = make_float4(acc[r][4], acc[r][5], acc[r][6], acc[r][7]);
        if (j < 64) {
            *reinterpret_cast<float4*>(&g_y[(size_t)n * 64 + j])     = o0;
            *reinterpret_cast<float4*>(&g_y[(size_t)n * 64 + j + 4]) = o1;
        } else {
            *reinterpret_cast<float4*>(&g_xr[(size_t)n * 64 + j - 64])     = o0;
            *reinterpret_cast<float4*>(&g_xr[(size_t)n * 64 + j - 64 + 4]) = o1;
        }
    }
}

// ---------------- kernel 3: edge scatter ------------------------------------
// 16 threads per edge; each thread moves one float4 of y[src] into agg[dst].
// NOTE: edge_index is int32 on the wire (JAX x64 disabled).
__global__ void edge_scatter(const int* __restrict__ ei) {
    int tid = threadIdx.x;
    int e = blockIdx.x * 16 + (tid >> 4);
    int t = tid & 15;
    if (e >= N_EDGES) return;
    int src = __ldg(&ei[e]);
    int dst = __ldg(&ei[N_EDGES + e]);

    const float4* ysrc = reinterpret_cast<const float4*>(g_y + (size_t)src * 64);
    float4 v = __ldg(ysrc + t);
    float* dptr = g_agg + (size_t)dst * 64 + t * 4;
    asm volatile("red.global.add.v4.f32 [%0], {%1, %2, %3, %4};"
                 :: "l"(dptr), "f"(v.x), "f"(v.y), "f"(v.z), "f"(v.w)
                 : "memory");
    if (t == 0) {
        float* dp = g_deg + dst;
        asm volatile("red.global.add.f32 [%0], %1;" :: "l"(dp), "f"(1.0f) : "memory");
    }
}

// ---------------- kernel 4: combine + per-graph pool ------------------------
#define POOL_BLOCKS 148
#define POOL_WARPS  (POOL_BLOCKS * 8)
#define POOL_CHUNK  ((N_NODES + POOL_WARPS - 1) / POOL_WARPS)
__global__ void combine_pool(const float* __restrict__ bl,
                             const int* __restrict__ batch) {
    int wid = (blockIdx.x * blockDim.x + threadIdx.x) >> 5;
    int lane = threadIdx.x & 31;
    int start = wid * POOL_CHUNK;
    if (start >= N_NODES) return;
    int end = min(start + POOL_CHUNK, N_NODES);

    float bl0 = bl[lane], bl1 = bl[lane + 32];
    float acc0 = 0.f, acc1 = 0.f, cnt = 0.f;
    int cur = batch[start];

    for (int n = start; n < end; n++) {
        int b = batch[n];
        if (b != cur) {
            atomicAdd(&g_gsum[cur * 64 + lane], acc0);
            atomicAdd(&g_gsum[cur * 64 + lane + 32], acc1);
            if (lane == 0) atomicAdd(&g_gcnt[cur], cnt);
            acc0 = acc1 = cnt = 0.f;
            cur = b;
        }
        float inv = 1.0f / fmaxf(g_deg[n], 1.0f);
        size_t base = (size_t)n * 64;
        float h0 = fmaxf(fmaf(g_agg[base + lane],      inv, g_xr[base + lane]      + bl0), 0.f);
        float h1 = fmaxf(fmaf(g_agg[base + lane + 32], inv, g_xr[base + lane + 32] + bl1), 0.f);
        acc0 += h0; acc1 += h1; cnt += 1.f;
    }
    atomicAdd(&g_gsum[cur * 64 + lane], acc0);
    atomicAdd(&g_gsum[cur * 64 + lane + 32], acc1);
    if (lane == 0) atomicAdd(&g_gcnt[cur], cnt);
}

// ---------------- kernel 5: final MLP (16 graphs, 1 block) ------------------
__global__ void final_mlp(const float* __restrict__ pk, const float* __restrict__ ck,
                          const float* __restrict__ Wp, const float* __restrict__ bp,
                          const float* __restrict__ Wc, const float* __restrict__ bc,
                          const float* __restrict__ Wh1, const float* __restrict__ bh1,
                          const float* __restrict__ Wh2, const float* __restrict__ bh2,
                          float* __restrict__ out) {
    __shared__ float z[NG][128];
    int w = threadIdx.x >> 5;       // graph id, 0..15
    int lane = threadIdx.x & 31;

    float cnt = fmaxf(g_gcnt[w], 1.0f);
    z[w][lane]      = g_gsum[w * 64 + lane] / cnt;
    z[w][lane + 32] = g_gsum[w * 64 + lane + 32] / cnt;

    // p = relu(pk @ Wp^T + bp): 32 outputs, one per lane
    float s = bp[lane];
#pragma unroll
    for (int k = 0; k < 7; k++) s = fmaf(pk[w * 7 + k], Wp[lane * 7 + k], s);
    z[w][64 + lane] = fmaxf(s, 0.f);

    s = bc[lane];
#pragma unroll
    for (int k = 0; k < 4; k++) s = fmaf(ck[w * 4 + k], Wc[lane * 4 + k], s);
    z[w][96 + lane] = fmaxf(s, 0.f);
    __syncwarp();

    float a0 = bh1[lane], a1 = bh1[lane + 32];
#pragma unroll 4
    for (int k = 0; k < 128; k++) {
        float zv = z[w][k];
        a0 = fmaf(zv, Wh1[lane * 128 + k], a0);
        a1 = fmaf(zv, Wh1[(lane + 32) * 128 + k], a1);
    }
    a0 = fmaxf(a0, 0.f);
    a1 = fmaxf(a1, 0.f);
    float r = a0 * Wh2[lane] + a1 * Wh2[lane + 32];
#pragma unroll
    for (int off = 16; off > 0; off >>= 1) r += __shfl_down_sync(0xffffffffu, r, off);
    if (lane == 0) out[w] = r + bh2[0];
}

// ---------------- launch ----------------------------------------------------
extern "C" void kernel_launch(void* const* d_in, const int* in_sizes, int n_in,
                              void* d_out, int out_size) {
    const float* x    = (const float*)d_in[0];
    const float* pk   = (const float*)d_in[1];
    const float* ck   = (const float*)d_in[2];
    const float* Wl   = (const float*)d_in[3];
    const float* bl   = (const float*)d_in[4];
    const float* Wr   = (const float*)d_in[5];
    const float* Wp   = (const float*)d_in[6];
    const float* bp   = (const float*)d_in[7];
    const float* Wc   = (const float*)d_in[8];
    const float* bc   = (const float*)d_in[9];
    const float* Wh1  = (const float*)d_in[10];
    const float* bh1  = (const float*)d_in[11];
    const float* Wh2  = (const float*)d_in[12];
    const float* bh2  = (const float*)d_in[13];
    const int*   ei   = (const int*)d_in[14];    // int32 (JAX x64 disabled)
    const int*   batch= (const int*)d_in[15];    // int32
    float* out = (float*)d_out;

    // 1. zero scratch
    zero_kernel<<<2048, 256>>>();

    // 2. node GEMM: y = x@Wl^T, xr = x@Wr^T
    int gemm_smem = (128 * 128 + GEMM_BM * 132) * (int)sizeof(float);
    cudaFuncSetAttribute(node_gemm, cudaFuncAttributeMaxDynamicSharedMemorySize, gemm_smem);
    int gemm_blocks = (N_NODES + GEMM_BM - 1) / GEMM_BM;
    node_gemm<<<gemm_blocks, 256, gemm_smem>>>(x, Wl, Wr);

    // 3. edge scatter (16 threads / edge, 16 edges / block)
    edge_scatter<<<(N_EDGES + 15) / 16, 256>>>(ei);

    // 4. combine + pool
    combine_pool<<<POOL_BLOCKS, 256>>>(bl, batch);

    // 5. final MLP
    final_mlp<<<1, 512>>>(pk, ck, Wp, bp, Wc, bc, Wh1, bh1, Wh2, bh2, out);

    (void)in_sizes; (void)n_in; (void)out_size;
}